// round 2
// baseline (speedup 1.0000x reference)
#include <cuda_runtime.h>

#define YS 7
#define YC 20
#define LAMBDA_COORD 5.0f
#define LAMBDA_NOOBJ 0.5f
#define YEPS 1e-6f

constexpr int BATCH = 16384;
constexpr int CELLS = BATCH * YS * YS;        // 802816
constexpr int TPB   = 256;                    // cells per block == threads per block
constexpr int NBLK  = CELLS / TPB;            // 3136 (exact)
constexpr int PRED_F = 30;                    // floats per cell (predictions)
constexpr int TGT_F  = 25;                    // floats per cell (targets)

__device__ float g_partials[NBLK];

__device__ __forceinline__ float iou_f(float ax, float ay, float aw, float ah,
                                       float bx, float by, float bw, float bh) {
    float ax1 = ax - aw * 0.5f, ax2 = ax + aw * 0.5f;
    float ay1 = ay - ah * 0.5f, ay2 = ay + ah * 0.5f;
    float bx1 = bx - bw * 0.5f, bx2 = bx + bw * 0.5f;
    float by1 = by - bh * 0.5f, by2 = by + bh * 0.5f;
    float iw = fmaxf(fminf(ax2, bx2) - fmaxf(ax1, bx1), 0.0f);
    float ih = fmaxf(fminf(ay2, by2) - fmaxf(ay1, by1), 0.0f);
    float inter = iw * ih;
    float area_a = fabsf(aw * ah);
    float area_b = fabsf(bw * bh);
    return inter / (area_a + area_b - inter + YEPS);
}

__device__ __forceinline__ float sqw(float w) {
    return sqrtf(fmaxf(w, YEPS));
}

__global__ __launch_bounds__(TPB) void yolo_main(const float* __restrict__ pred,
                                                 const float* __restrict__ tgt) {
    __shared__ float sp[TPB * PRED_F];   // 30720 B
    __shared__ float st[TPB * TGT_F];    // 25600 B
    __shared__ float swarp[TPB / 32];

    const long long cell0 = (long long)blockIdx.x * TPB;
    const float4* __restrict__ pbase = (const float4*)(pred + cell0 * PRED_F);
    const float4* __restrict__ tbase = (const float4*)(tgt  + cell0 * TGT_F);

    // Coalesced float4 staging (tile sizes are multiples of 4 floats; bases 16B aligned)
    float4* sp4 = (float4*)sp;
    float4* st4 = (float4*)st;
    #pragma unroll
    for (int i = threadIdx.x; i < (TPB * PRED_F) / 4; i += TPB) sp4[i] = pbase[i];
    #pragma unroll
    for (int i = threadIdx.x; i < (TPB * TGT_F) / 4; i += TPB) st4[i] = tbase[i];
    __syncthreads();

    const float* p = sp + threadIdx.x * PRED_F;
    const float* t = st + threadIdx.x * TGT_F;

    // Class loss
    float cls = 0.0f;
    #pragma unroll
    for (int c = 0; c < YC; c++) {
        float d = p[c] - t[c];
        cls = fmaf(d, d, cls);
    }

    float b1x = p[20], b1y = p[21], b1w = p[22], b1h = p[23], b1c = p[24];
    float b2x = p[25], b2y = p[26], b2w = p[27], b2h = p[28], b2c = p[29];
    float tx  = t[20], ty  = t[21], tw  = t[22], th  = t[23], tc  = t[24];

    float obj = (t[20] == 1.0f) ? 1.0f : 0.0f;

    float iou1 = iou_f(b1x, b1y, b1w, b1h, tx, ty, tw, th);
    float iou2 = iou_f(b2x, b2y, b2w, b2h, tx, ty, tw, th);
    bool use1 = iou1 > iou2;

    float rx = use1 ? b1x : b2x;
    float ry = use1 ? b1y : b2y;
    float rw = use1 ? b1w : b2w;
    float rh = use1 ? b1h : b2h;
    float rc = use1 ? b1c : b2c;
    float other_conf = use1 ? b2c : b1c;

    float dx = rx - tx, dy = ry - ty;
    float dw = sqw(rw) - sqw(tw);
    float dh = sqw(rh) - sqw(th);
    float coord = LAMBDA_COORD * (dx * dx + dy * dy + dw * dw + dh * dh);
    float obj_conf = (rc - tc) * (rc - tc);
    float noobj_in = LAMBDA_NOOBJ * other_conf * other_conf;
    float noobj_out = LAMBDA_NOOBJ * (b1c * b1c + b2c * b2c);

    float loss = obj * (coord + obj_conf + cls + noobj_in) + (1.0f - obj) * noobj_out;

    // Block reduction (8 warps)
    #pragma unroll
    for (int o = 16; o > 0; o >>= 1)
        loss += __shfl_down_sync(0xffffffffu, loss, o);
    if ((threadIdx.x & 31) == 0) swarp[threadIdx.x >> 5] = loss;
    __syncthreads();
    if (threadIdx.x == 0) {
        float s = 0.0f;
        #pragma unroll
        for (int w = 0; w < TPB / 32; w++) s += swarp[w];
        g_partials[blockIdx.x] = s;
    }
}

__global__ __launch_bounds__(1024) void yolo_reduce(float* __restrict__ out) {
    __shared__ float sm[32];
    float s = 0.0f;
    for (int i = threadIdx.x; i < NBLK; i += 1024) s += g_partials[i];
    #pragma unroll
    for (int o = 16; o > 0; o >>= 1)
        s += __shfl_down_sync(0xffffffffu, s, o);
    if ((threadIdx.x & 31) == 0) sm[threadIdx.x >> 5] = s;
    __syncthreads();
    if (threadIdx.x < 32) {
        s = sm[threadIdx.x];
        #pragma unroll
        for (int o = 16; o > 0; o >>= 1)
            s += __shfl_down_sync(0xffffffffu, s, o);
        if (threadIdx.x == 0) out[0] = s / (float)BATCH;
    }
}

extern "C" void kernel_launch(void* const* d_in, const int* in_sizes, int n_in,
                              void* d_out, int out_size) {
    const float* pred = (const float*)d_in[0];
    const float* tgt  = (const float*)d_in[1];
    float* out = (float*)d_out;
    yolo_main<<<NBLK, TPB>>>(pred, tgt);
    yolo_reduce<<<1, 1024>>>(out);
}